// round 4
// baseline (speedup 1.0000x reference)
#include <cuda_runtime.h>
#include <cstdint>

#define N_NODES 100000
#define IN_DIM  128
#define EMB     64
#define NCLS    18
#define MAX_E   3200000

// ---------------- scratch (static device globals; no allocs) ----------------
__device__ int   g_cnt [N_NODES];     // in-degree (excl self loop)
__device__ int   g_rowp[N_NODES];     // CSR row start
__device__ int   g_cur [N_NODES];     // fill cursor
__device__ float g_dis [N_NODES];     // rsqrt(deg incl self loop)
__device__ float g_h1  [N_NODES * EMB];
__device__ float g_r1  [N_NODES * EMB];   // relu(agg1 + b1)
__device__ float g_h2  [N_NODES * NCLS];
__device__ int2  g_csr [MAX_E];       // (src, bitcast norm), dst-sorted

// ---------------- kernels ---------------------------------------------------

__global__ void k_zero() {
    int i = blockIdx.x * blockDim.x + threadIdx.x;
    if (i < N_NODES) g_cnt[i] = 0;
}

// in-degree count (edge_index is int32 per harness dtype rules)
__global__ void k_deg(const int* __restrict__ ei, int E) {
    int e = blockIdx.x * blockDim.x + threadIdx.x;
    if (e < E) {
        int d = __ldg(ei + E + e);
        if ((unsigned)d < N_NODES) atomicAdd(&g_cnt[d], 1);
    }
}

// single-block exclusive scan over g_cnt -> g_rowp/g_cur; also g_dis
__global__ void k_scan() {
    __shared__ int ssum[1024];
    const int CH = (N_NODES + 1023) / 1024;   // 98
    int t  = threadIdx.x;
    int lo = t * CH;
    int hi = min(lo + CH, N_NODES);
    int s = 0;
    for (int i = lo; i < hi; ++i) s += g_cnt[i];
    ssum[t] = s;
    __syncthreads();
    for (int off = 1; off < 1024; off <<= 1) {
        int u = (t >= off) ? ssum[t - off] : 0;
        __syncthreads();
        ssum[t] += u;
        __syncthreads();
    }
    int run = ssum[t] - s;   // exclusive base for this thread's chunk
    for (int i = lo; i < hi; ++i) {
        int c = g_cnt[i];
        g_rowp[i] = run;
        g_cur [i] = run;
        g_dis [i] = rsqrtf((float)(c + 1));
        run += c;
    }
}

// scatter (src, norm) into dst-sorted CSR slots
__global__ void k_fill(const int* __restrict__ ei, int E) {
    int e = blockIdx.x * blockDim.x + threadIdx.x;
    if (e >= E) return;
    int s = __ldg(ei + e);
    int d = __ldg(ei + E + e);
    if ((unsigned)s >= N_NODES) s = 0;
    if ((unsigned)d >= N_NODES) d = 0;
    float nrm = g_dis[s] * g_dis[d];
    int pos = atomicAdd(&g_cur[d], 1);
    g_csr[pos] = make_int2(s, __float_as_int(nrm));
}

// h1 = x @ W1   (100000x128 @ 128x64), W1 staged in smem
#define G1_ROWS 64
__global__ void k_gemm1(const float* __restrict__ x, const float* __restrict__ W1) {
    __shared__ float sW[IN_DIM * EMB];  // 32 KB
    for (int i = threadIdx.x; i < IN_DIM * EMB; i += blockDim.x) sW[i] = W1[i];
    __syncthreads();
    int col  = threadIdx.x;                   // 0..63
    int row0 = blockIdx.x * G1_ROWS;
    int row1 = min(row0 + G1_ROWS, N_NODES);
    for (int row = row0; row < row1; ++row) {
        const float4* x4 = (const float4*)(x + (size_t)row * IN_DIM);
        float acc = 0.f;
#pragma unroll
        for (int k4 = 0; k4 < IN_DIM / 4; ++k4) {
            float4 xv = x4[k4];
            int k = k4 * 4;
            acc += xv.x * sW[(k + 0) * EMB + col];
            acc += xv.y * sW[(k + 1) * EMB + col];
            acc += xv.z * sW[(k + 2) * EMB + col];
            acc += xv.w * sW[(k + 3) * EMB + col];
        }
        g_h1[(size_t)row * EMB + col] = acc;
    }
}

// layer-1 aggregation (gather over CSR) fused with +b1, relu.
// 64-thread group per node, thread owns one column.
__global__ void k_agg1(const float* __restrict__ b1) {
    int node = blockIdx.x * 4 + (threadIdx.x >> 6);
    int c    = threadIdx.x & 63;
    if (node >= N_NODES) return;
    float dn  = g_dis[node];
    float acc = g_h1[(size_t)node * EMB + c] * dn * dn;   // self loop
    float acc2 = 0.f;
    int beg = g_rowp[node];
    int cnt = g_cnt [node];
    const int2* p = g_csr + beg;
    int i = 0;
    for (; i + 2 <= cnt; i += 2) {
        int2 m0 = __ldg(p + i);
        int2 m1 = __ldg(p + i + 1);
        acc  += __int_as_float(m0.y) * __ldg(&g_h1[(size_t)m0.x * EMB + c]);
        acc2 += __int_as_float(m1.y) * __ldg(&g_h1[(size_t)m1.x * EMB + c]);
    }
    if (i < cnt) {
        int2 m = __ldg(p + i);
        acc += __int_as_float(m.y) * __ldg(&g_h1[(size_t)m.x * EMB + c]);
    }
    g_r1[(size_t)node * EMB + c] = fmaxf(acc + acc2 + b1[c], 0.f);
}

// h2 = r1 @ W2   (100000x64 @ 64x18); block: 16 nodes x 18 cols
__global__ void k_gemm2(const float* __restrict__ W2) {
    __shared__ float sA[16 * EMB];
    __shared__ float sW[EMB * NCLS];
    int t = threadIdx.y * NCLS + threadIdx.x;  // 0..287
    int node0 = blockIdx.x * 16;
    for (int idx = t; idx < 16 * EMB; idx += 16 * NCLS) {
        int r = idx >> 6, cc = idx & 63;
        int node = node0 + r;
        sA[idx] = (node < N_NODES) ? g_r1[(size_t)node * EMB + cc] : 0.f;
    }
    for (int idx = t; idx < EMB * NCLS; idx += 16 * NCLS) sW[idx] = W2[idx];
    __syncthreads();
    int c    = threadIdx.x;        // 0..17
    int node = node0 + threadIdx.y;
    if (node >= N_NODES) return;
    float acc = 0.f;
#pragma unroll
    for (int k = 0; k < EMB; ++k) acc += sA[threadIdx.y * EMB + k] * sW[k * NCLS + c];
    g_h2[(size_t)node * NCLS + c] = acc;
}

// layer-2 aggregation fused with +b2 and log_softmax. Warp per node.
__global__ void k_agg2_final(const float* __restrict__ b2, float* __restrict__ out,
                             int write_logits) {
    int node = blockIdx.x * 8 + (threadIdx.x >> 5);
    int lane = threadIdx.x & 31;
    if (node >= N_NODES) return;
    bool act = lane < NCLS;
    float dn  = g_dis[node];
    float acc = act ? g_h2[(size_t)node * NCLS + lane] * dn * dn : 0.f;
    int beg = g_rowp[node];
    int cnt = g_cnt [node];
    const int2* p = g_csr + beg;
    float acc2 = 0.f;
    int i = 0;
    for (; i + 2 <= cnt; i += 2) {
        int2 m0 = __ldg(p + i);       // warp-uniform address -> broadcast
        int2 m1 = __ldg(p + i + 1);
        if (act) {
            acc  += __int_as_float(m0.y) * __ldg(&g_h2[(size_t)m0.x * NCLS + lane]);
            acc2 += __int_as_float(m1.y) * __ldg(&g_h2[(size_t)m1.x * NCLS + lane]);
        }
    }
    if (i < cnt) {
        int2 m = __ldg(p + i);
        if (act) acc += __int_as_float(m.y) * __ldg(&g_h2[(size_t)m.x * NCLS + lane]);
    }
    float v = acc + acc2 + (act ? b2[lane] : 0.f);
    float mx = act ? v : -1e30f;
#pragma unroll
    for (int off = 16; off >= 1; off >>= 1)
        mx = fmaxf(mx, __shfl_xor_sync(0xffffffffu, mx, off));
    float s = act ? __expf(v - mx) : 0.f;
#pragma unroll
    for (int off = 16; off >= 1; off >>= 1)
        s += __shfl_xor_sync(0xffffffffu, s, off);
    float lse = mx + __logf(s);
    if (act) {
        out[(size_t)node * NCLS + lane] = v - lse;
        if (write_logits)
            out[(size_t)N_NODES * NCLS + (size_t)node * NCLS + lane] = v;
    }
}

// ---------------- launch -----------------------------------------------------
extern "C" void kernel_launch(void* const* d_in, const int* in_sizes, int n_in,
                              void* d_out, int out_size) {
    const float* x  = (const float*)d_in[0];
    const int*   ei = (const int*)d_in[1];     // int64 downcast to int32 by harness
    const float* W1 = (const float*)d_in[2];
    const float* b1 = (const float*)d_in[3];
    const float* W2 = (const float*)d_in[4];
    const float* b2 = (const float*)d_in[5];
    float* out = (float*)d_out;

    int E = in_sizes[1] / 2;
    if (E > MAX_E) E = MAX_E;
    int write_logits = (out_size >= 2 * N_NODES * NCLS) ? 1 : 0;

    k_zero<<<(N_NODES + 255) / 256, 256>>>();
    k_deg <<<(E + 255) / 256, 256>>>(ei, E);
    k_scan<<<1, 1024>>>();
    k_fill<<<(E + 255) / 256, 256>>>(ei, E);

    k_gemm1<<<(N_NODES + G1_ROWS - 1) / G1_ROWS, EMB>>>(x, W1);
    k_agg1 <<<(N_NODES + 3) / 4, 256>>>(b1);

    k_gemm2<<<(N_NODES + 15) / 16, dim3(NCLS, 16)>>>(W2);
    k_agg2_final<<<(N_NODES + 7) / 8, 256>>>(b2, out, write_logits);
}